// round 12
// baseline (speedup 1.0000x reference)
#include <cuda_runtime.h>
#include <math.h>

// Problem constants (fixed by setup_inputs)
#define TOTAL_N 32768
#define NB      64      // B graphs
#define NG      512     // nodes per graph
#define NV      64      // virtual nodes
#define NH      256     // hidden
#define NIN     128
#define NOUT    10
#define EMAX    (64 * 16384)

// ---------------- scratch (device globals; no allocs allowed) ----------------
__device__ __align__(16) float d_bufA[TOTAL_N * NH];   // t1
__device__ __align__(16) float d_bufB[TOTAL_N * NH];   // hw / t
__device__ __align__(16) float d_bufC[TOTAL_N * NH];   // g
__device__ __align__(16) float d_mwn[NB * NG * NV];
__device__ __align__(16) float d_vn[NB * NV * NH];
__device__ __align__(16) float d_vn1[NB * NV * NH];
__device__ __align__(16) float d_gf[NB * NH];
__device__ __align__(16) float d_gf1[NB * NH];
__device__ __align__(16) float d_Wcomb[NIN * NH];      // W_emb @ W_gcn
__device__ __align__(16) float d_bcomb[NH];            // b_emb @ W_gcn
// CSR scratch
__device__ __align__(16) int d_cnt[TOTAL_N];           // in-degree counts
__device__ __align__(16) int d_off[TOTAL_N + 1];       // row offsets
__device__ __align__(16) int d_cur[TOTAL_N];           // fill cursors
__device__ __align__(16) int d_csr[EMAX];              // src ids sorted by dst

__device__ __forceinline__ unsigned f2tf32(float f) {
    unsigned u;
    asm("cvt.rna.tf32.f32 %0, %1;" : "=r"(u) : "f"(f));
    return u;
}

// ============ TF32 tensor-core GEMM (R10 version): C = act(A@W + bias) =======
// BM=128, BN=128, BK=32; 256 threads = 8 warps in 2x4; warp tile 64x32.
// A staged FRAGMENT-MAJOR in smem (one LDS.128 per mma A-frag, stride 132);
// B row-major with 136-word stride. Static smem -> 2 CTAs/SM for overlap.
#define AS_W 132
#define BS_W 136
template<bool RELU, bool BIAS>
__global__ void __launch_bounds__(256) tgemm(
    const float* __restrict__ A, const float* __restrict__ W,
    const float* __restrict__ bias, float* __restrict__ C,
    int M, int K, int Nc)
{
    __shared__ __align__(16) unsigned As[32 * AS_W];  // 8 i-tiles x 4 ks
    __shared__ __align__(16) unsigned Bs[32 * BS_W];

    const int tid  = threadIdx.x;
    const int lane = tid & 31;
    const int warp = tid >> 5;
    const int wm = warp >> 2;      // 0..1 (64-row slab)
    const int wn = warp & 3;       // 0..3 (32-col slab)
    const int m0 = blockIdx.y * 128;
    const int n0 = blockIdx.x * 128;
    const int lr = lane >> 2;      // 0..7
    const int lc = lane & 3;       // 0..3

    float acc[4][4][4];
    #pragma unroll
    for (int i = 0; i < 4; i++)
        #pragma unroll
        for (int j = 0; j < 4; j++)
            #pragma unroll
            for (int r = 0; r < 4; r++) acc[i][j][r] = 0.f;

    for (int k0 = 0; k0 < K; k0 += 32) {
        // ---- stage A 128x32 fragment-major (tf32 convert in flight) ----
        #pragma unroll
        for (int it = 0; it < 4; it++) {
            int f = tid + it * 256;            // 0..1023 float4s
            int row = f >> 3, c4 = (f & 7) * 4;
            float4 v = *(const float4*)&A[(size_t)(m0 + row) * K + k0 + c4];
            int i  = row >> 4;
            int r8 = row & 15;
            int ks = c4 >> 3;
            int reg = (r8 >> 3) + ((c4 >> 1) & 2);   // (r8>=8) + 2*(c>=4)
            unsigned base = (unsigned)((i * 4 + ks) * AS_W + (r8 & 7) * 16 + reg);
            As[base + 0]  = f2tf32(v.x);
            As[base + 4]  = f2tf32(v.y);
            As[base + 8]  = f2tf32(v.z);
            As[base + 12] = f2tf32(v.w);
        }
        // ---- stage B 32x128 row-major ----
        #pragma unroll
        for (int it = 0; it < 4; it++) {
            int f = tid + it * 256;
            int row = f >> 5, c4 = (f & 31) * 4;
            float4 v = *(const float4*)&W[(size_t)(k0 + row) * Nc + n0 + c4];
            uint4 u;
            u.x = f2tf32(v.x); u.y = f2tf32(v.y);
            u.z = f2tf32(v.z); u.w = f2tf32(v.w);
            *(uint4*)&Bs[row * BS_W + c4] = u;
        }
        __syncthreads();

        #pragma unroll
        for (int ks = 0; ks < 4; ks++) {
            uint4 af[4];
            unsigned bf[4][2];
            #pragma unroll
            for (int ii = 0; ii < 4; ii++)
                af[ii] = *(const uint4*)&As[((wm * 4 + ii) * 4 + ks) * AS_W + lane * 4];
            #pragma unroll
            for (int j = 0; j < 4; j++) {
                int c = wn * 32 + j * 8 + lr;
                bf[j][0] = Bs[(ks * 8 + lc) * BS_W + c];
                bf[j][1] = Bs[(ks * 8 + lc + 4) * BS_W + c];
            }
            #pragma unroll
            for (int i = 0; i < 4; i++)
                #pragma unroll
                for (int j = 0; j < 4; j++)
                    asm volatile(
                        "mma.sync.aligned.m16n8k8.row.col.f32.tf32.tf32.f32 "
                        "{%0,%1,%2,%3}, {%4,%5,%6,%7}, {%8,%9}, {%0,%1,%2,%3};"
                        : "+f"(acc[i][j][0]), "+f"(acc[i][j][1]),
                          "+f"(acc[i][j][2]), "+f"(acc[i][j][3])
                        : "r"(af[i].x), "r"(af[i].y), "r"(af[i].z), "r"(af[i].w),
                          "r"(bf[j][0]), "r"(bf[j][1]));
        }
        __syncthreads();
    }

    // ---- epilogue: bias + relu, float2 stores ----
    #pragma unroll
    for (int j = 0; j < 4; j++) {
        int c = n0 + wn * 32 + j * 8 + 2 * lc;
        float b0 = 0.f, b1 = 0.f;
        if (BIAS) { b0 = bias[c]; b1 = bias[c + 1]; }
        #pragma unroll
        for (int i = 0; i < 4; i++) {
            int r = m0 + wm * 64 + i * 16 + lr;
            float v0 = acc[i][j][0] + b0;
            float v1 = acc[i][j][1] + b1;
            float v2 = acc[i][j][2] + b0;
            float v3 = acc[i][j][3] + b1;
            if (RELU) {
                v0 = fmaxf(v0, 0.f); v1 = fmaxf(v1, 0.f);
                v2 = fmaxf(v2, 0.f); v3 = fmaxf(v3, 0.f);
            }
            *(float2*)&C[(size_t)r * Nc + c]       = make_float2(v0, v1);
            *(float2*)&C[(size_t)(r + 8) * Nc + c] = make_float2(v2, v3);
        }
    }
}

// ========= batched TF32 mma: vn[b] = mwn[b]^T (64x512) @ g[b] (512x256) ======
// grid (2, NB); block 256 = 8 warps (2m x 4n); tile M=64, N=128, BK=32.
__global__ void __launch_bounds__(256) vn_mma(const float* __restrict__ g)
{
    __shared__ __align__(16) unsigned As[16 * AS_W];  // 4 i-tiles x 4 ks
    __shared__ __align__(16) unsigned Bs[32 * BS_W];

    const int b   = blockIdx.y;
    const int h0  = blockIdx.x * 128;
    const int tid = threadIdx.x;
    const int lane = tid & 31;
    const int warp = tid >> 5;
    const int wm = warp >> 2;      // 0..1 (32-row slab)
    const int wn = warp & 3;       // 0..3
    const int lr = lane >> 2;
    const int lc = lane & 3;

    const float* mb = d_mwn + (size_t)b * NG * NV;
    const float* gb = g + (size_t)b * NG * NH;

    float acc[2][4][4];
    #pragma unroll
    for (int i = 0; i < 2; i++)
        #pragma unroll
        for (int j = 0; j < 4; j++)
            #pragma unroll
            for (int r = 0; r < 4; r++) acc[i][j][r] = 0.f;

    for (int k0 = 0; k0 < NG; k0 += 32) {
        // ---- stage A 64(v) x 32(k=n) from mwn[n][v] (transposed read) ----
        #pragma unroll
        for (int it = 0; it < 2; it++) {
            int f = tid + it * 256;            // 0..511 float4s
            int kk = f >> 4, v4 = (f & 15) * 4;
            float4 v = *(const float4*)&mb[(size_t)(k0 + kk) * NV + v4];
            int i  = v4 >> 4;
            int ks = kk >> 3;
            int reg = ((v4 & 15) >> 3) + ((kk >> 1) & 2);
            int kc3 = kk & 3;
            unsigned base = (unsigned)((i * 4 + ks) * AS_W + kc3 * 4 + reg);
            As[base + ((v4 & 7) + 0) * 16] = f2tf32(v.x);
            As[base + ((v4 & 7) + 1) * 16] = f2tf32(v.y);
            As[base + ((v4 & 7) + 2) * 16] = f2tf32(v.z);
            As[base + ((v4 & 7) + 3) * 16] = f2tf32(v.w);
        }
        // ---- stage B 32(k=n) x 128(h) ----
        #pragma unroll
        for (int it = 0; it < 4; it++) {
            int f = tid + it * 256;
            int row = f >> 5, c4 = (f & 31) * 4;
            float4 v = *(const float4*)&gb[(size_t)(k0 + row) * NH + h0 + c4];
            uint4 u;
            u.x = f2tf32(v.x); u.y = f2tf32(v.y);
            u.z = f2tf32(v.z); u.w = f2tf32(v.w);
            *(uint4*)&Bs[row * BS_W + c4] = u;
        }
        __syncthreads();

        #pragma unroll
        for (int ks = 0; ks < 4; ks++) {
            uint4 af[2];
            unsigned bf[4][2];
            #pragma unroll
            for (int ii = 0; ii < 2; ii++)
                af[ii] = *(const uint4*)&As[((wm * 2 + ii) * 4 + ks) * AS_W + lane * 4];
            #pragma unroll
            for (int j = 0; j < 4; j++) {
                int c = wn * 32 + j * 8 + lr;
                bf[j][0] = Bs[(ks * 8 + lc) * BS_W + c];
                bf[j][1] = Bs[(ks * 8 + lc + 4) * BS_W + c];
            }
            #pragma unroll
            for (int i = 0; i < 2; i++)
                #pragma unroll
                for (int j = 0; j < 4; j++)
                    asm volatile(
                        "mma.sync.aligned.m16n8k8.row.col.f32.tf32.tf32.f32 "
                        "{%0,%1,%2,%3}, {%4,%5,%6,%7}, {%8,%9}, {%0,%1,%2,%3};"
                        : "+f"(acc[i][j][0]), "+f"(acc[i][j][1]),
                          "+f"(acc[i][j][2]), "+f"(acc[i][j][3])
                        : "r"(af[i].x), "r"(af[i].y), "r"(af[i].z), "r"(af[i].w),
                          "r"(bf[j][0]), "r"(bf[j][1]));
        }
        __syncthreads();
    }

    float* vb = d_vn + (size_t)b * NV * NH;
    #pragma unroll
    for (int j = 0; j < 4; j++) {
        int c = h0 + wn * 32 + j * 8 + 2 * lc;
        #pragma unroll
        for (int i = 0; i < 2; i++) {
            int r = wm * 32 + i * 16 + lr;
            *(float2*)&vb[(size_t)r * NH + c]       = make_float2(acc[i][j][0], acc[i][j][1]);
            *(float2*)&vb[(size_t)(r + 8) * NH + c] = make_float2(acc[i][j][2], acc[i][j][3]);
        }
    }
}

// ---------------- exact fp32 SGEMM (small mats): 64x64 tile, 4x4/thread ------
template<bool RELU, bool BIAS>
__global__ void __launch_bounds__(256) sgemm64(
    const float* __restrict__ A, const float* __restrict__ W,
    const float* __restrict__ bias, float* __restrict__ C,
    int M, int K, int Nc)
{
    __shared__ __align__(16) float As[16][68];
    __shared__ __align__(16) float Bs[16][64];

    const int m0 = blockIdx.y * 64;
    const int n0 = blockIdx.x * 64;
    const int tid = threadIdx.x;
    const int tx = tid & 15;
    const int ty = tid >> 4;

    const int la_m = tid >> 2;
    const int la_k = (tid & 3) * 4;
    const int lb_k = tid >> 4;
    const int lb_n = (tid & 15) * 4;

    const float* Aptr = A + (size_t)(m0 + la_m) * K + la_k;
    const float* Wptr = W + (size_t)lb_k * Nc + n0 + lb_n;

    float acc[4][4] = {};

    for (int k0 = 0; k0 < K; k0 += 16) {
        float4 av = *(const float4*)(Aptr + k0);
        As[la_k + 0][la_m] = av.x;
        As[la_k + 1][la_m] = av.y;
        As[la_k + 2][la_m] = av.z;
        As[la_k + 3][la_m] = av.w;
        *(float4*)&Bs[lb_k][lb_n] = *(const float4*)(Wptr + (size_t)k0 * Nc);
        __syncthreads();
        #pragma unroll
        for (int k = 0; k < 16; k++) {
            float4 a4 = *(const float4*)&As[k][ty * 4];
            float4 b4 = *(const float4*)&Bs[k][tx * 4];
            float a[4] = {a4.x, a4.y, a4.z, a4.w};
            float b[4] = {b4.x, b4.y, b4.z, b4.w};
            #pragma unroll
            for (int i = 0; i < 4; i++)
                #pragma unroll
                for (int j = 0; j < 4; j++)
                    acc[i][j] += a[i] * b[j];
        }
        __syncthreads();
    }

    float bv[4] = {0.f, 0.f, 0.f, 0.f};
    if (BIAS) {
        float4 b4 = *(const float4*)&bias[n0 + tx * 4];
        bv[0] = b4.x; bv[1] = b4.y; bv[2] = b4.z; bv[3] = b4.w;
    }
    #pragma unroll
    for (int i = 0; i < 4; i++) {
        int m = m0 + ty * 4 + i;
        float v0 = acc[i][0] + bv[0];
        float v1 = acc[i][1] + bv[1];
        float v2 = acc[i][2] + bv[2];
        float v3 = acc[i][3] + bv[3];
        if (RELU) {
            v0 = fmaxf(v0, 0.f); v1 = fmaxf(v1, 0.f);
            v2 = fmaxf(v2, 0.f); v3 = fmaxf(v3, 0.f);
        }
        float4 r; r.x = v0; r.y = v1; r.z = v2; r.w = v3;
        *(float4*)&C[(size_t)m * Nc + n0 + tx * 4] = r;
    }
}

// ---------------- b_comb = b_emb @ W_gcn -------------------------------------
__global__ void bcomb_kernel(const float* __restrict__ b_emb,
                             const float* __restrict__ W_gcn)
{
    int n = threadIdx.x;  // 256
    float s = 0.f;
    for (int k = 0; k < NH; k++) s += b_emb[k] * W_gcn[k * NH + n];
    d_bcomb[n] = s;
}

// ================= CSR build ================================================
__global__ void zero_cnt_kernel()
{
    int i = blockIdx.x * blockDim.x + threadIdx.x;
    if (i < TOTAL_N) d_cnt[i] = 0;
}

__global__ void hist_kernel(const int* __restrict__ dst, int E)
{
    int i = blockIdx.x * blockDim.x + threadIdx.x;
    if (i < E) atomicAdd(&d_cnt[dst[i]], 1);
}

// single block, 1024 threads: exclusive scan of d_cnt -> d_off, d_cur
__global__ void __launch_bounds__(1024) scan_kernel()
{
    __shared__ int sm[1024];
    int tid = threadIdx.x;
    int base = tid * 32;
    int loc[32];
    int s = 0;
    #pragma unroll
    for (int i = 0; i < 32; i++) { loc[i] = s; s += d_cnt[base + i]; }
    sm[tid] = s;
    __syncthreads();
    for (int st = 1; st < 1024; st <<= 1) {
        int add = (tid >= st) ? sm[tid - st] : 0;
        __syncthreads();
        sm[tid] += add;
        __syncthreads();
    }
    int pre = sm[tid] - s;
    #pragma unroll
    for (int i = 0; i < 32; i++) {
        int v = pre + loc[i];
        d_off[base + i] = v;
        d_cur[base + i] = v;
    }
    if (tid == 1023) d_off[TOTAL_N] = sm[1023];
}

__global__ void fill_kernel(const int* __restrict__ src,
                            const int* __restrict__ dst, int E)
{
    int i = blockIdx.x * blockDim.x + threadIdx.x;
    if (i < E) {
        int d = dst[i];
        int pos = atomicAdd(&d_cur[d], 1);
        d_csr[pos] = src[i];
    }
}

// ======== aggregation: per-graph smem-tiled gather, fused GCN epilogue =======
// grid (4 h-chunks, NB graphs); block 256 = 8 warps. Each block stages its
// graph's hw slice (512 x 64 f32 = 128KB) + rsqrt(deg) (2KB) into smem; each
// dst-warp then sums its CSR neighbors via conflict-free LDS.64 (smem BW
// replaces the L2/LTS cap; hw is read from L2 exactly once per chunk).
// Summation order identical to the previous gather -> bit-identical results.
#define AGG_SMEM ((NG * 64 + NG) * 4)   // 133120 B
__global__ void __launch_bounds__(256) agg_kernel(const float* __restrict__ b_gcn)
{
    extern __shared__ __align__(16) float sm_f[];
    float* smhw  = sm_f;             // [512][64]
    float* snorm = sm_f + NG * 64;   // [512]

    const int b    = blockIdx.y;
    const int h0   = blockIdx.x * 64;
    const int tid  = threadIdx.x;
    const int warp = tid >> 5;
    const int lane = tid & 31;

    // stage hw slice + per-node scale
    const float* hwb = d_bufB + (size_t)b * NG * NH + h0;
    for (int i = tid; i < NG * 16; i += 256) {
        int n = i >> 4, q = (i & 15) * 4;
        *(float4*)&smhw[n * 64 + q] = *(const float4*)&hwb[(size_t)n * NH + q];
    }
    for (int i = tid; i < NG; i += 256)
        snorm[i] = rsqrtf((float)(d_cnt[b * NG + i] + 1));
    __syncthreads();

    const float2 bg = *(const float2*)&b_gcn[h0 + lane * 2];

    for (int n = warp; n < NG; n += 8) {
        const int gd  = b * NG + n;
        const int beg = d_off[gd];
        const int end = d_off[gd + 1];

        float ax = 0.f, ay = 0.f;
        for (int j0 = beg; j0 < end; j0 += 32) {
            int cnt = end - j0; if (cnt > 32) cnt = 32;
            int sl = 0;
            if (j0 + lane < end) sl = d_csr[j0 + lane] - b * NG;  // local src id
            for (int t = 0; t < cnt; t++) {
                int ss = __shfl_sync(0xffffffffu, sl, t);
                float scc = snorm[ss];
                float2 v = *(const float2*)&smhw[ss * 64 + lane * 2];
                ax += v.x * scc;
                ay += v.y * scc;
            }
        }

        float degd = (float)(d_cnt[gd] + 1);
        float dinv = rsqrtf(degd);
        float idg  = 1.0f / degd;
        float2 sv = *(const float2*)&smhw[n * 64 + lane * 2];
        float2 o;
        o.x = fmaxf(dinv * ax + sv.x * idg + bg.x, 0.f);
        o.y = fmaxf(dinv * ay + sv.y * idg + bg.y, 0.f);
        *(float2*)&d_bufC[(size_t)gd * NH + h0 + lane * 2] = o;
    }
}

// ===== fused proto + pn + att + mwn: one block per graph =====================
__global__ void __launch_bounds__(256) pam_kernel(const float* __restrict__ t,
                                                  const float* __restrict__ ew)
{
    __shared__ float proto_s[NH];
    __shared__ float red[NH];
    __shared__ float att_s[NG];
    __shared__ float pn_s;

    const int b = blockIdx.x;
    const int h = threadIdx.x;       // 256
    const int warp = h >> 5;
    const int lane = h & 31;
    const float* tb = t + (size_t)b * NG * NH;

    // proto = mean_n t
    float s = 0.f;
    for (int n = 0; n < NG; n++) s += tb[(size_t)n * NH + h];
    float p = s * (1.0f / NG);
    proto_s[h] = p;
    red[h] = p * p;
    __syncthreads();
    for (int st = 128; st > 0; st >>= 1) {
        if (h < st) red[h] += red[h + st];
        __syncthreads();
    }
    if (h == 0) pn_s = fmaxf(sqrtf(red[0]), 1e-8f);
    __syncthreads();

    // att per node (warp per node)
    for (int n = warp; n < NG; n += 8) {
        const float* tr = tb + (size_t)n * NH;
        float dot = 0.f, sq = 0.f;
        #pragma unroll
        for (int i = lane; i < NH; i += 32) {
            float tv = tr[i];
            dot += tv * proto_s[i];
            sq  += tv * tv;
        }
        #pragma unroll
        for (int o = 16; o; o >>= 1) {
            dot += __shfl_xor_sync(0xffffffffu, dot, o);
            sq  += __shfl_xor_sync(0xffffffffu, sq, o);
        }
        if (lane == 0) {
            float tn = fmaxf(sqrtf(sq), 1e-8f);
            att_s[n] = 0.5f * (1.0f + dot / (tn * pn_s));
        }
    }
    __syncthreads();

    // mwn (warp per node row)
    for (int n = warp; n < NG; n += 8) {
        const float* e = ew + (size_t)(b * NG + n) * NV;
        float e0 = e[lane];
        float e1 = e[lane + 32];
        float sm = e0 + e1;
        #pragma unroll
        for (int o = 16; o; o >>= 1) sm += __shfl_xor_sync(0xffffffffu, sm, o);
        float a = att_s[n];
        float rs = sm * a;
        float inv = a / ((rs == 0.0f) ? 1.0f : rs);
        float* mw = d_mwn + (size_t)(b * NG + n) * NV;
        mw[lane]      = e0 * inv;
        mw[lane + 32] = e1 * inv;
    }
}

// ---------------- gf = mean_v vn2 --------------------------------------------
__global__ void gf_kernel(const float* __restrict__ vn2)
{
    int b = blockIdx.x;
    int h = threadIdx.x;
    float s = 0.f;
    for (int v = 0; v < NV; v++) s += vn2[((size_t)b * NV + v) * NH + h];
    d_gf[b * NH + h] = s * (1.0f / NV);
}

// ---------------- out = gf1 @ mW2 + mb2 --------------------------------------
__global__ void out_kernel(const float* __restrict__ mW2,
                           const float* __restrict__ mb2,
                           float* __restrict__ out)
{
    int b = blockIdx.x;
    int w = threadIdx.x >> 5;
    int lane = threadIdx.x & 31;
    if (w >= NOUT) return;
    const float* gr = d_gf1 + b * NH;
    float s = 0.f;
    #pragma unroll
    for (int i = lane; i < NH; i += 32) s += gr[i] * mW2[i * NOUT + w];
    #pragma unroll
    for (int o = 16; o; o >>= 1) s += __shfl_xor_sync(0xffffffffu, s, o);
    if (lane == 0) out[b * NOUT + w] = s + mb2[w];
}

// =============================================================================
extern "C" void kernel_launch(void* const* d_in, const int* in_sizes, int n_in,
                              void* d_out, int out_size)
{
    const float* x      = (const float*)d_in[0];
    const int*   esrc   = (const int*)  d_in[1];
    const int*   edst   = (const int*)  d_in[2];
    const float* W_emb  = (const float*)d_in[3];
    const float* b_emb  = (const float*)d_in[4];
    const float* W_gcn  = (const float*)d_in[5];
    const float* b_gcn  = (const float*)d_in[6];
    const float* aW1    = (const float*)d_in[7];
    const float* ab1    = (const float*)d_in[8];
    const float* aW2    = (const float*)d_in[9];
    const float* ab2    = (const float*)d_in[10];
    const float* vW1    = (const float*)d_in[11];
    const float* vb1    = (const float*)d_in[12];
    const float* vW2    = (const float*)d_in[13];
    const float* vb2    = (const float*)d_in[14];
    const float* mW1    = (const float*)d_in[15];
    const float* mb1    = (const float*)d_in[16];
    const float* mW2    = (const float*)d_in[17];
    const float* mb2    = (const float*)d_in[18];
    const float* ew     = (const float*)d_in[19];
    const int E = in_sizes[1];

    float *bufA, *bufB, *bufC, *pvn, *pvn1, *pgf, *pgf1, *pWc, *pbc;
    cudaGetSymbolAddress((void**)&bufA, d_bufA);
    cudaGetSymbolAddress((void**)&bufB, d_bufB);
    cudaGetSymbolAddress((void**)&bufC, d_bufC);
    cudaGetSymbolAddress((void**)&pvn,  d_vn);
    cudaGetSymbolAddress((void**)&pvn1, d_vn1);
    cudaGetSymbolAddress((void**)&pgf,  d_gf);
    cudaGetSymbolAddress((void**)&pgf1, d_gf1);
    cudaGetSymbolAddress((void**)&pWc,  d_Wcomb);
    cudaGetSymbolAddress((void**)&pbc,  d_bcomb);

    // allow 130KB dynamic smem on agg (idempotent host-side attribute)
    static bool attr_done = false;
    if (!attr_done) {
        cudaFuncSetAttribute(agg_kernel,
                             cudaFuncAttributeMaxDynamicSharedMemorySize, AGG_SMEM);
        attr_done = true;
    }

    dim3 g_wc(NH / 64, NIN / 64);          // (4, 2)  exact fp32 fold
    dim3 g_big(NH / 128, TOTAL_N / 128);   // (2, 256) tf32
    dim3 g_vnm(NH / 128, (NB * NV) / 128); // (2, 32)  tf32
    dim3 g_gf(NH / 64, 1);                 // (4, 1)  exact fp32
    dim3 g_vne(2, NB);                     // vn_mma
    dim3 g_agg(4, NB);                     // agg chunks

    // 0) fold first two linear layers (exact fp32): Wcomb = W_emb @ W_gcn
    sgemm64<false, false><<<g_wc, 256>>>(W_emb, W_gcn, nullptr, pWc, NIN, NH, NH);
    bcomb_kernel<<<1, 256>>>(b_emb, W_gcn);
    zero_cnt_kernel<<<TOTAL_N / 1024, 1024>>>();
    // (launch index 3 -> gets profiled by ncu)
    tgemm<false, true><<<g_big, 256>>>(x, pWc, pbc, bufB, TOTAL_N, NIN, NH);
    // CSR build
    hist_kernel<<<(E + 1023) / 1024, 1024>>>(edst, E);
    scan_kernel<<<1, 1024>>>();
    fill_kernel<<<(E + 1023) / 1024, 1024>>>(esrc, edst, E);
    // smem-tiled gather-aggregate + fused GCN epilogue  -> bufC = g (fp32)
    agg_kernel<<<g_agg, 256, AGG_SMEM>>>(b_gcn);
    // t1 = relu(g @ aW1 + ab1)                     -> bufA  (tf32)
    tgemm<true, true><<<g_big, 256>>>(bufC, aW1, ab1, bufA, TOTAL_N, NH, NH);
    // t = t1 @ aW2 + ab2                           -> bufB  (tf32)
    tgemm<false, true><<<g_big, 256>>>(bufA, aW2, ab2, bufB, TOTAL_N, NH, NH);
    // proto / pn / att / mwn fused
    pam_kernel<<<NB, 256>>>(bufB, ew);
    // vn = einsum(bnv,bnh->bvh)                    -> d_vn (tf32 mma)
    vn_mma<<<g_vne, 256>>>(bufC);
    // vn1 = relu(vn @ vW1 + vb1); vn2 = vn1 @ vW2 + vb2   (tf32)
    tgemm<true, true><<<g_vnm, 256>>>(pvn, vW1, vb1, pvn1, NB * NV, NH, NH);
    tgemm<false, true><<<g_vnm, 256>>>(pvn1, vW2, vb2, pvn, NB * NV, NH, NH);
    // gf = mean_v vn2; gf1 = relu(gf @ mW1 + mb1); out   (exact fp32)
    gf_kernel<<<NB, 256>>>(pvn);
    sgemm64<true, true><<<g_gf, 256>>>(pgf, mW1, mb1, pgf1, 64, NH, NH);
    out_kernel<<<NB, 320>>>(mW2, mb2, (float*)d_out);
}

// round 15
// speedup vs baseline: 1.8478x; 1.8478x over previous
#include <cuda_runtime.h>
#include <math.h>

// Problem constants (fixed by setup_inputs)
#define TOTAL_N 32768
#define NB      64      // B graphs
#define NG      512     // nodes per graph
#define NV      64      // virtual nodes
#define NH      256     // hidden
#define NIN     128
#define NOUT    10
#define EMAX    (64 * 16384)

// ---------------- scratch (device globals; no allocs allowed) ----------------
__device__ __align__(16) float d_bufA[TOTAL_N * NH];   // t1
__device__ __align__(16) float d_bufB[TOTAL_N * NH];   // hw / t
__device__ __align__(16) float d_bufC[TOTAL_N * NH];   // g
__device__ __align__(16) float d_mwn[NB * NG * NV];
__device__ __align__(16) float d_vn[NB * NV * NH];
__device__ __align__(16) float d_vn1[NB * NV * NH];
__device__ __align__(16) float d_gf[NB * NH];
__device__ __align__(16) float d_gf1[NB * NH];
__device__ __align__(16) float d_Wcomb[NIN * NH];      // W_emb @ W_gcn
__device__ __align__(16) float d_bcomb[NH];            // b_emb @ W_gcn
// CSR scratch
__device__ __align__(16) int d_cnt[TOTAL_N];           // in-degree counts
__device__ __align__(16) int d_off[TOTAL_N + 1];       // row offsets
__device__ __align__(16) int d_cur[TOTAL_N];           // fill cursors
__device__ __align__(16) int d_csr[EMAX];              // src ids sorted by dst

__device__ __forceinline__ unsigned f2tf32(float f) {
    unsigned u;
    asm("cvt.rna.tf32.f32 %0, %1;" : "=r"(u) : "f"(f));
    return u;
}

// ============ TF32 tensor-core GEMM (R10 version): C = act(A@W + bias) =======
// BM=128, BN=128, BK=32; 256 threads = 8 warps in 2x4; warp tile 64x32.
// A staged FRAGMENT-MAJOR in smem (one LDS.128 per mma A-frag, stride 132);
// B row-major with 136-word stride. Static smem -> 2 CTAs/SM for overlap.
#define AS_W 132
#define BS_W 136
template<bool RELU, bool BIAS>
__global__ void __launch_bounds__(256) tgemm(
    const float* __restrict__ A, const float* __restrict__ W,
    const float* __restrict__ bias, float* __restrict__ C,
    int M, int K, int Nc)
{
    __shared__ __align__(16) unsigned As[32 * AS_W];  // 8 i-tiles x 4 ks
    __shared__ __align__(16) unsigned Bs[32 * BS_W];

    const int tid  = threadIdx.x;
    const int lane = tid & 31;
    const int warp = tid >> 5;
    const int wm = warp >> 2;      // 0..1 (64-row slab)
    const int wn = warp & 3;       // 0..3 (32-col slab)
    const int m0 = blockIdx.y * 128;
    const int n0 = blockIdx.x * 128;
    const int lr = lane >> 2;      // 0..7
    const int lc = lane & 3;       // 0..3

    float acc[4][4][4];
    #pragma unroll
    for (int i = 0; i < 4; i++)
        #pragma unroll
        for (int j = 0; j < 4; j++)
            #pragma unroll
            for (int r = 0; r < 4; r++) acc[i][j][r] = 0.f;

    for (int k0 = 0; k0 < K; k0 += 32) {
        // ---- stage A 128x32 fragment-major (tf32 convert in flight) ----
        #pragma unroll
        for (int it = 0; it < 4; it++) {
            int f = tid + it * 256;            // 0..1023 float4s
            int row = f >> 3, c4 = (f & 7) * 4;
            float4 v = *(const float4*)&A[(size_t)(m0 + row) * K + k0 + c4];
            int i  = row >> 4;
            int r8 = row & 15;
            int ks = c4 >> 3;
            int reg = (r8 >> 3) + ((c4 >> 1) & 2);   // (r8>=8) + 2*(c>=4)
            unsigned base = (unsigned)((i * 4 + ks) * AS_W + (r8 & 7) * 16 + reg);
            As[base + 0]  = f2tf32(v.x);
            As[base + 4]  = f2tf32(v.y);
            As[base + 8]  = f2tf32(v.z);
            As[base + 12] = f2tf32(v.w);
        }
        // ---- stage B 32x128 row-major ----
        #pragma unroll
        for (int it = 0; it < 4; it++) {
            int f = tid + it * 256;
            int row = f >> 5, c4 = (f & 31) * 4;
            float4 v = *(const float4*)&W[(size_t)(k0 + row) * Nc + n0 + c4];
            uint4 u;
            u.x = f2tf32(v.x); u.y = f2tf32(v.y);
            u.z = f2tf32(v.z); u.w = f2tf32(v.w);
            *(uint4*)&Bs[row * BS_W + c4] = u;
        }
        __syncthreads();

        #pragma unroll
        for (int ks = 0; ks < 4; ks++) {
            uint4 af[4];
            unsigned bf[4][2];
            #pragma unroll
            for (int ii = 0; ii < 4; ii++)
                af[ii] = *(const uint4*)&As[((wm * 4 + ii) * 4 + ks) * AS_W + lane * 4];
            #pragma unroll
            for (int j = 0; j < 4; j++) {
                int c = wn * 32 + j * 8 + lr;
                bf[j][0] = Bs[(ks * 8 + lc) * BS_W + c];
                bf[j][1] = Bs[(ks * 8 + lc + 4) * BS_W + c];
            }
            #pragma unroll
            for (int i = 0; i < 4; i++)
                #pragma unroll
                for (int j = 0; j < 4; j++)
                    asm volatile(
                        "mma.sync.aligned.m16n8k8.row.col.f32.tf32.tf32.f32 "
                        "{%0,%1,%2,%3}, {%4,%5,%6,%7}, {%8,%9}, {%0,%1,%2,%3};"
                        : "+f"(acc[i][j][0]), "+f"(acc[i][j][1]),
                          "+f"(acc[i][j][2]), "+f"(acc[i][j][3])
                        : "r"(af[i].x), "r"(af[i].y), "r"(af[i].z), "r"(af[i].w),
                          "r"(bf[j][0]), "r"(bf[j][1]));
        }
        __syncthreads();
    }

    // ---- epilogue: bias + relu, float2 stores ----
    #pragma unroll
    for (int j = 0; j < 4; j++) {
        int c = n0 + wn * 32 + j * 8 + 2 * lc;
        float b0 = 0.f, b1 = 0.f;
        if (BIAS) { b0 = bias[c]; b1 = bias[c + 1]; }
        #pragma unroll
        for (int i = 0; i < 4; i++) {
            int r = m0 + wm * 64 + i * 16 + lr;
            float v0 = acc[i][j][0] + b0;
            float v1 = acc[i][j][1] + b1;
            float v2 = acc[i][j][2] + b0;
            float v3 = acc[i][j][3] + b1;
            if (RELU) {
                v0 = fmaxf(v0, 0.f); v1 = fmaxf(v1, 0.f);
                v2 = fmaxf(v2, 0.f); v3 = fmaxf(v3, 0.f);
            }
            *(float2*)&C[(size_t)r * Nc + c]       = make_float2(v0, v1);
            *(float2*)&C[(size_t)(r + 8) * Nc + c] = make_float2(v2, v3);
        }
    }
}

// ========= batched TF32 mma: vn[b] = mwn[b]^T (64x512) @ g[b] (512x256) ======
// grid (2, NB); block 256 = 8 warps (2m x 4n); tile M=64, N=128, BK=32.
__global__ void __launch_bounds__(256) vn_mma(const float* __restrict__ g)
{
    __shared__ __align__(16) unsigned As[16 * AS_W];  // 4 i-tiles x 4 ks
    __shared__ __align__(16) unsigned Bs[32 * BS_W];

    const int b   = blockIdx.y;
    const int h0  = blockIdx.x * 128;
    const int tid = threadIdx.x;
    const int lane = tid & 31;
    const int warp = tid >> 5;
    const int wm = warp >> 2;      // 0..1 (32-row slab)
    const int wn = warp & 3;       // 0..3
    const int lr = lane >> 2;
    const int lc = lane & 3;

    const float* mb = d_mwn + (size_t)b * NG * NV;
    const float* gb = g + (size_t)b * NG * NH;

    float acc[2][4][4];
    #pragma unroll
    for (int i = 0; i < 2; i++)
        #pragma unroll
        for (int j = 0; j < 4; j++)
            #pragma unroll
            for (int r = 0; r < 4; r++) acc[i][j][r] = 0.f;

    for (int k0 = 0; k0 < NG; k0 += 32) {
        // ---- stage A 64(v) x 32(k=n) from mwn[n][v] (transposed read) ----
        #pragma unroll
        for (int it = 0; it < 2; it++) {
            int f = tid + it * 256;            // 0..511 float4s
            int kk = f >> 4, v4 = (f & 15) * 4;
            float4 v = *(const float4*)&mb[(size_t)(k0 + kk) * NV + v4];
            int i  = v4 >> 4;
            int ks = kk >> 3;
            int reg = ((v4 & 15) >> 3) + ((kk >> 1) & 2);
            int kc3 = kk & 3;
            unsigned base = (unsigned)((i * 4 + ks) * AS_W + kc3 * 4 + reg);
            As[base + ((v4 & 7) + 0) * 16] = f2tf32(v.x);
            As[base + ((v4 & 7) + 1) * 16] = f2tf32(v.y);
            As[base + ((v4 & 7) + 2) * 16] = f2tf32(v.z);
            As[base + ((v4 & 7) + 3) * 16] = f2tf32(v.w);
        }
        // ---- stage B 32(k=n) x 128(h) ----
        #pragma unroll
        for (int it = 0; it < 4; it++) {
            int f = tid + it * 256;
            int row = f >> 5, c4 = (f & 31) * 4;
            float4 v = *(const float4*)&gb[(size_t)(k0 + row) * NH + h0 + c4];
            uint4 u;
            u.x = f2tf32(v.x); u.y = f2tf32(v.y);
            u.z = f2tf32(v.z); u.w = f2tf32(v.w);
            *(uint4*)&Bs[row * BS_W + c4] = u;
        }
        __syncthreads();

        #pragma unroll
        for (int ks = 0; ks < 4; ks++) {
            uint4 af[2];
            unsigned bf[4][2];
            #pragma unroll
            for (int ii = 0; ii < 2; ii++)
                af[ii] = *(const uint4*)&As[((wm * 2 + ii) * 4 + ks) * AS_W + lane * 4];
            #pragma unroll
            for (int j = 0; j < 4; j++) {
                int c = wn * 32 + j * 8 + lr;
                bf[j][0] = Bs[(ks * 8 + lc) * BS_W + c];
                bf[j][1] = Bs[(ks * 8 + lc + 4) * BS_W + c];
            }
            #pragma unroll
            for (int i = 0; i < 2; i++)
                #pragma unroll
                for (int j = 0; j < 4; j++)
                    asm volatile(
                        "mma.sync.aligned.m16n8k8.row.col.f32.tf32.tf32.f32 "
                        "{%0,%1,%2,%3}, {%4,%5,%6,%7}, {%8,%9}, {%0,%1,%2,%3};"
                        : "+f"(acc[i][j][0]), "+f"(acc[i][j][1]),
                          "+f"(acc[i][j][2]), "+f"(acc[i][j][3])
                        : "r"(af[i].x), "r"(af[i].y), "r"(af[i].z), "r"(af[i].w),
                          "r"(bf[j][0]), "r"(bf[j][1]));
        }
        __syncthreads();
    }

    float* vb = d_vn + (size_t)b * NV * NH;
    #pragma unroll
    for (int j = 0; j < 4; j++) {
        int c = h0 + wn * 32 + j * 8 + 2 * lc;
        #pragma unroll
        for (int i = 0; i < 2; i++) {
            int r = wm * 32 + i * 16 + lr;
            *(float2*)&vb[(size_t)r * NH + c]       = make_float2(acc[i][j][0], acc[i][j][1]);
            *(float2*)&vb[(size_t)(r + 8) * NH + c] = make_float2(acc[i][j][2], acc[i][j][3]);
        }
    }
}

// ---------------- exact fp32 SGEMM (small mats): 64x64 tile, 4x4/thread ------
template<bool RELU, bool BIAS>
__global__ void __launch_bounds__(256) sgemm64(
    const float* __restrict__ A, const float* __restrict__ W,
    const float* __restrict__ bias, float* __restrict__ C,
    int M, int K, int Nc)
{
    __shared__ __align__(16) float As[16][68];
    __shared__ __align__(16) float Bs[16][64];

    const int m0 = blockIdx.y * 64;
    const int n0 = blockIdx.x * 64;
    const int tid = threadIdx.x;
    const int tx = tid & 15;
    const int ty = tid >> 4;

    const int la_m = tid >> 2;
    const int la_k = (tid & 3) * 4;
    const int lb_k = tid >> 4;
    const int lb_n = (tid & 15) * 4;

    const float* Aptr = A + (size_t)(m0 + la_m) * K + la_k;
    const float* Wptr = W + (size_t)lb_k * Nc + n0 + lb_n;

    float acc[4][4] = {};

    for (int k0 = 0; k0 < K; k0 += 16) {
        float4 av = *(const float4*)(Aptr + k0);
        As[la_k + 0][la_m] = av.x;
        As[la_k + 1][la_m] = av.y;
        As[la_k + 2][la_m] = av.z;
        As[la_k + 3][la_m] = av.w;
        *(float4*)&Bs[lb_k][lb_n] = *(const float4*)(Wptr + (size_t)k0 * Nc);
        __syncthreads();
        #pragma unroll
        for (int k = 0; k < 16; k++) {
            float4 a4 = *(const float4*)&As[k][ty * 4];
            float4 b4 = *(const float4*)&Bs[k][tx * 4];
            float a[4] = {a4.x, a4.y, a4.z, a4.w};
            float b[4] = {b4.x, b4.y, b4.z, b4.w};
            #pragma unroll
            for (int i = 0; i < 4; i++)
                #pragma unroll
                for (int j = 0; j < 4; j++)
                    acc[i][j] += a[i] * b[j];
        }
        __syncthreads();
    }

    float bv[4] = {0.f, 0.f, 0.f, 0.f};
    if (BIAS) {
        float4 b4 = *(const float4*)&bias[n0 + tx * 4];
        bv[0] = b4.x; bv[1] = b4.y; bv[2] = b4.z; bv[3] = b4.w;
    }
    #pragma unroll
    for (int i = 0; i < 4; i++) {
        int m = m0 + ty * 4 + i;
        float v0 = acc[i][0] + bv[0];
        float v1 = acc[i][1] + bv[1];
        float v2 = acc[i][2] + bv[2];
        float v3 = acc[i][3] + bv[3];
        if (RELU) {
            v0 = fmaxf(v0, 0.f); v1 = fmaxf(v1, 0.f);
            v2 = fmaxf(v2, 0.f); v3 = fmaxf(v3, 0.f);
        }
        float4 r; r.x = v0; r.y = v1; r.z = v2; r.w = v3;
        *(float4*)&C[(size_t)m * Nc + n0 + tx * 4] = r;
    }
}

// ---------------- b_comb = b_emb @ W_gcn -------------------------------------
__global__ void bcomb_kernel(const float* __restrict__ b_emb,
                             const float* __restrict__ W_gcn)
{
    int n = threadIdx.x;  // 256
    float s = 0.f;
    for (int k = 0; k < NH; k++) s += b_emb[k] * W_gcn[k * NH + n];
    d_bcomb[n] = s;
}

// ================= CSR build ================================================
__global__ void zero_cnt_kernel()
{
    int i = blockIdx.x * blockDim.x + threadIdx.x;
    if (i < TOTAL_N) d_cnt[i] = 0;
}

__global__ void hist_kernel(const int* __restrict__ dst, int E)
{
    int i = blockIdx.x * blockDim.x + threadIdx.x;
    if (i < E) atomicAdd(&d_cnt[dst[i]], 1);
}

// single block, 1024 threads: exclusive scan of d_cnt -> d_off, d_cur
__global__ void __launch_bounds__(1024) scan_kernel()
{
    __shared__ int sm[1024];
    int tid = threadIdx.x;
    int base = tid * 32;
    int loc[32];
    int s = 0;
    #pragma unroll
    for (int i = 0; i < 32; i++) { loc[i] = s; s += d_cnt[base + i]; }
    sm[tid] = s;
    __syncthreads();
    for (int st = 1; st < 1024; st <<= 1) {
        int add = (tid >= st) ? sm[tid - st] : 0;
        __syncthreads();
        sm[tid] += add;
        __syncthreads();
    }
    int pre = sm[tid] - s;
    #pragma unroll
    for (int i = 0; i < 32; i++) {
        int v = pre + loc[i];
        d_off[base + i] = v;
        d_cur[base + i] = v;
    }
    if (tid == 1023) d_off[TOTAL_N] = sm[1023];
}

__global__ void fill_kernel(const int* __restrict__ src,
                            const int* __restrict__ dst, int E)
{
    int i = blockIdx.x * blockDim.x + threadIdx.x;
    if (i < E) {
        int d = dst[i];
        int pos = atomicAdd(&d_cur[d], 1);
        d_csr[pos] = src[i];
    }
}

// ======== aggregation: warp per dst node, fused GCN epilogue =================
// R10 structure, but neighbors processed two per iteration -> 4 independent
// LDG.128s in flight (2x MLP). Accumulation order identical to R10
// (t then t+1, sequential adds) -> bit-identical numerics.
__global__ void __launch_bounds__(256) agg_kernel(const float* __restrict__ b_gcn)
{
    const int d    = blockIdx.x * 8 + (threadIdx.x >> 5);
    const int lane = threadIdx.x & 31;
    const int beg = d_off[d];
    const int end = d_off[d + 1];

    float4 a0 = make_float4(0.f, 0.f, 0.f, 0.f);
    float4 a1 = make_float4(0.f, 0.f, 0.f, 0.f);

    for (int j0 = beg; j0 < end; j0 += 32) {
        int n = end - j0; if (n > 32) n = 32;
        int s = 0; float sc = 0.f;
        if (j0 + lane < end) {
            s = d_csr[j0 + lane];
            sc = rsqrtf((float)(d_cnt[s] + 1));
        }
        int t = 0;
        for (; t + 1 < n; t += 2) {
            int ss0 = __shfl_sync(0xffffffffu, s, t);
            float c0 = __shfl_sync(0xffffffffu, sc, t);
            int ss1 = __shfl_sync(0xffffffffu, s, t + 1);
            float c1 = __shfl_sync(0xffffffffu, sc, t + 1);
            const float4* r0 = (const float4*)&d_bufB[(size_t)ss0 * NH + lane * 8];
            const float4* r1 = (const float4*)&d_bufB[(size_t)ss1 * NH + lane * 8];
            float4 p0 = r0[0], p1 = r0[1];
            float4 q0 = r1[0], q1 = r1[1];
            a0.x += p0.x * c0; a0.y += p0.y * c0;
            a0.z += p0.z * c0; a0.w += p0.w * c0;
            a1.x += p1.x * c0; a1.y += p1.y * c0;
            a1.z += p1.z * c0; a1.w += p1.w * c0;
            a0.x += q0.x * c1; a0.y += q0.y * c1;
            a0.z += q0.z * c1; a0.w += q0.w * c1;
            a1.x += q1.x * c1; a1.y += q1.y * c1;
            a1.z += q1.z * c1; a1.w += q1.w * c1;
        }
        if (t < n) {
            int ss = __shfl_sync(0xffffffffu, s, t);
            float scc = __shfl_sync(0xffffffffu, sc, t);
            const float4* r = (const float4*)&d_bufB[(size_t)ss * NH + lane * 8];
            float4 v0 = r[0], v1 = r[1];
            a0.x += v0.x * scc; a0.y += v0.y * scc;
            a0.z += v0.z * scc; a0.w += v0.w * scc;
            a1.x += v1.x * scc; a1.y += v1.y * scc;
            a1.z += v1.z * scc; a1.w += v1.w * scc;
        }
    }

    float degd = (float)(d_cnt[d] + 1);
    float dinv = rsqrtf(degd);
    float idg  = 1.0f / degd;
    const float4* rs = (const float4*)&d_bufB[(size_t)d * NH + lane * 8];
    float4 s0 = rs[0], s1 = rs[1];
    const float4* bg = (const float4*)&b_gcn[lane * 8];
    float4 b0 = bg[0], b1 = bg[1];

    float4 o0, o1;
    o0.x = fmaxf(dinv * a0.x + s0.x * idg + b0.x, 0.f);
    o0.y = fmaxf(dinv * a0.y + s0.y * idg + b0.y, 0.f);
    o0.z = fmaxf(dinv * a0.z + s0.z * idg + b0.z, 0.f);
    o0.w = fmaxf(dinv * a0.w + s0.w * idg + b0.w, 0.f);
    o1.x = fmaxf(dinv * a1.x + s1.x * idg + b1.x, 0.f);
    o1.y = fmaxf(dinv * a1.y + s1.y * idg + b1.y, 0.f);
    o1.z = fmaxf(dinv * a1.z + s1.z * idg + b1.z, 0.f);
    o1.w = fmaxf(dinv * a1.w + s1.w * idg + b1.w, 0.f);

    float4* out = (float4*)&d_bufC[(size_t)d * NH + lane * 8];
    out[0] = o0;
    out[1] = o1;
}

// ===== fused proto + pn + att + mwn: one block per graph =====================
__global__ void __launch_bounds__(256) pam_kernel(const float* __restrict__ t,
                                                  const float* __restrict__ ew)
{
    __shared__ float proto_s[NH];
    __shared__ float red[NH];
    __shared__ float att_s[NG];
    __shared__ float pn_s;

    const int b = blockIdx.x;
    const int h = threadIdx.x;       // 256
    const int warp = h >> 5;
    const int lane = h & 31;
    const float* tb = t + (size_t)b * NG * NH;

    // proto = mean_n t
    float s = 0.f;
    for (int n = 0; n < NG; n++) s += tb[(size_t)n * NH + h];
    float p = s * (1.0f / NG);
    proto_s[h] = p;
    red[h] = p * p;
    __syncthreads();
    for (int st = 128; st > 0; st >>= 1) {
        if (h < st) red[h] += red[h + st];
        __syncthreads();
    }
    if (h == 0) pn_s = fmaxf(sqrtf(red[0]), 1e-8f);
    __syncthreads();

    // att per node (warp per node)
    for (int n = warp; n < NG; n += 8) {
        const float* tr = tb + (size_t)n * NH;
        float dot = 0.f, sq = 0.f;
        #pragma unroll
        for (int i = lane; i < NH; i += 32) {
            float tv = tr[i];
            dot += tv * proto_s[i];
            sq  += tv * tv;
        }
        #pragma unroll
        for (int o = 16; o; o >>= 1) {
            dot += __shfl_xor_sync(0xffffffffu, dot, o);
            sq  += __shfl_xor_sync(0xffffffffu, sq, o);
        }
        if (lane == 0) {
            float tn = fmaxf(sqrtf(sq), 1e-8f);
            att_s[n] = 0.5f * (1.0f + dot / (tn * pn_s));
        }
    }
    __syncthreads();

    // mwn (warp per node row)
    for (int n = warp; n < NG; n += 8) {
        const float* e = ew + (size_t)(b * NG + n) * NV;
        float e0 = e[lane];
        float e1 = e[lane + 32];
        float sm = e0 + e1;
        #pragma unroll
        for (int o = 16; o; o >>= 1) sm += __shfl_xor_sync(0xffffffffu, sm, o);
        float a = att_s[n];
        float rs = sm * a;
        float inv = a / ((rs == 0.0f) ? 1.0f : rs);
        float* mw = d_mwn + (size_t)(b * NG + n) * NV;
        mw[lane]      = e0 * inv;
        mw[lane + 32] = e1 * inv;
    }
}

// ---------------- gf = mean_v vn2 --------------------------------------------
__global__ void gf_kernel(const float* __restrict__ vn2)
{
    int b = blockIdx.x;
    int h = threadIdx.x;
    float s = 0.f;
    for (int v = 0; v < NV; v++) s += vn2[((size_t)b * NV + v) * NH + h];
    d_gf[b * NH + h] = s * (1.0f / NV);
}

// ---------------- out = gf1 @ mW2 + mb2 --------------------------------------
__global__ void out_kernel(const float* __restrict__ mW2,
                           const float* __restrict__ mb2,
                           float* __restrict__ out)
{
    int b = blockIdx.x;
    int w = threadIdx.x >> 5;
    int lane = threadIdx.x & 31;
    if (w >= NOUT) return;
    const float* gr = d_gf1 + b * NH;
    float s = 0.f;
    #pragma unroll
    for (int i = lane; i < NH; i += 32) s += gr[i] * mW2[i * NOUT + w];
    #pragma unroll
    for (int o = 16; o; o >>= 1) s += __shfl_xor_sync(0xffffffffu, s, o);
    if (lane == 0) out[b * NOUT + w] = s + mb2[w];
}

// =============================================================================
extern "C" void kernel_launch(void* const* d_in, const int* in_sizes, int n_in,
                              void* d_out, int out_size)
{
    const float* x      = (const float*)d_in[0];
    const int*   esrc   = (const int*)  d_in[1];
    const int*   edst   = (const int*)  d_in[2];
    const float* W_emb  = (const float*)d_in[3];
    const float* b_emb  = (const float*)d_in[4];
    const float* W_gcn  = (const float*)d_in[5];
    const float* b_gcn  = (const float*)d_in[6];
    const float* aW1    = (const float*)d_in[7];
    const float* ab1    = (const float*)d_in[8];
    const float* aW2    = (const float*)d_in[9];
    const float* ab2    = (const float*)d_in[10];
    const float* vW1    = (const float*)d_in[11];
    const float* vb1    = (const float*)d_in[12];
    const float* vW2    = (const float*)d_in[13];
    const float* vb2    = (const float*)d_in[14];
    const float* mW1    = (const float*)d_in[15];
    const float* mb1    = (const float*)d_in[16];
    const float* mW2    = (const float*)d_in[17];
    const float* mb2    = (const float*)d_in[18];
    const float* ew     = (const float*)d_in[19];
    const int E = in_sizes[1];

    float *bufA, *bufB, *bufC, *pvn, *pvn1, *pgf, *pgf1, *pWc, *pbc;
    cudaGetSymbolAddress((void**)&bufA, d_bufA);
    cudaGetSymbolAddress((void**)&bufB, d_bufB);
    cudaGetSymbolAddress((void**)&bufC, d_bufC);
    cudaGetSymbolAddress((void**)&pvn,  d_vn);
    cudaGetSymbolAddress((void**)&pvn1, d_vn1);
    cudaGetSymbolAddress((void**)&pgf,  d_gf);
    cudaGetSymbolAddress((void**)&pgf1, d_gf1);
    cudaGetSymbolAddress((void**)&pWc,  d_Wcomb);
    cudaGetSymbolAddress((void**)&pbc,  d_bcomb);

    dim3 g_wc(NH / 64, NIN / 64);          // (4, 2)  exact fp32 fold
    dim3 g_big(NH / 128, TOTAL_N / 128);   // (2, 256) tf32
    dim3 g_vnm(NH / 128, (NB * NV) / 128); // (2, 32)  tf32
    dim3 g_gf(NH / 64, 1);                 // (4, 1)  exact fp32
    dim3 g_vne(2, NB);                     // vn_mma

    // 0) fold first two linear layers (exact fp32): Wcomb = W_emb @ W_gcn
    sgemm64<false, false><<<g_wc, 256>>>(W_emb, W_gcn, nullptr, pWc, NIN, NH, NH);
    bcomb_kernel<<<1, 256>>>(b_emb, W_gcn);
    zero_cnt_kernel<<<TOTAL_N / 1024, 1024>>>();
    // (launch index 3 -> gets profiled by ncu)
    tgemm<false, true><<<g_big, 256>>>(x, pWc, pbc, bufB, TOTAL_N, NIN, NH);
    // CSR build
    hist_kernel<<<(E + 1023) / 1024, 1024>>>(edst, E);
    scan_kernel<<<1, 1024>>>();
    fill_kernel<<<(E + 1023) / 1024, 1024>>>(esrc, edst, E);
    // gather-aggregate + fused GCN epilogue        -> bufC = g (exact fp32)
    agg_kernel<<<TOTAL_N / 8, 256>>>(b_gcn);
    // t1 = relu(g @ aW1 + ab1)                     -> bufA  (tf32)
    tgemm<true, true><<<g_big, 256>>>(bufC, aW1, ab1, bufA, TOTAL_N, NH, NH);
    // t = t1 @ aW2 + ab2                           -> bufB  (tf32)
    tgemm<false, true><<<g_big, 256>>>(bufA, aW2, ab2, bufB, TOTAL_N, NH, NH);
    // proto / pn / att / mwn fused
    pam_kernel<<<NB, 256>>>(bufB, ew);
    // vn = einsum(bnv,bnh->bvh)                    -> d_vn (tf32 mma)
    vn_mma<<<g_vne, 256>>>(bufC);
    // vn1 = relu(vn @ vW1 + vb1); vn2 = vn1 @ vW2 + vb2   (tf32)
    tgemm<true, true><<<g_vnm, 256>>>(pvn, vW1, vb1, pvn1, NB * NV, NH, NH);
    tgemm<false, true><<<g_vnm, 256>>>(pvn1, vW2, vb2, pvn, NB * NV, NH, NH);
    // gf = mean_v vn2; gf1 = relu(gf @ mW1 + mb1); out   (exact fp32)
    gf_kernel<<<NB, 256>>>(pvn);
    sgemm64<true, true><<<g_gf, 256>>>(pgf, mW1, mb1, pgf1, 64, NH, NH);
    out_kernel<<<NB, 320>>>(mW2, mb2, (float*)d_out);
}